// round 1
// baseline (speedup 1.0000x reference)
#include <cuda_runtime.h>

// Problem constants
#define DM   512      // d_model
#define TL   512      // seq len
#define BB   2        // batch
#define HN   8        // heads
#define WN   16       // waves
#define HD   64       // head dim
#define MTOK 1024     // B*T tokens

// Range reduction constants (2-term Cody-Waite around 2*pi)
#define INV2PI 0.15915494309189535f
#define MAGIC  12582912.0f            // 1.5 * 2^23
#define C2PI_A 6.2831854820251465f    // float(2*pi)
#define C2PI_B (-1.7484555e-7f)       // 2*pi - C2PI_A

// ---------------- scratch (static __device__, no allocation) ----------------
__device__ float g_freq [BB*HN*TL*WN];   // [b*8+h][t][w]
__device__ float g_phase[BB*HN*TL*WN];
__device__ float g_amp  [BB*HN*TL*WN];
__device__ float g_s2   [BB*HN*TL];      // sum_w amp^2
__device__ float g_v    [BB*HN*TL*HD];   // [b*8+h][t][d]
__device__ float g_att  [MTOK*DM];       // attention output, [b*T+t][h*64+d]

// ---------------- fp32 tiled GEMM core: 64x64 tile, BK=16, 256 thr --------
// C[m0+64][n0+64] += A[1024,512] * W[512,N]
__device__ __forceinline__ void gemm_core(const float* __restrict__ A,
                                          const float* __restrict__ W,
                                          int N, int m0, int n0,
                                          float acc[4][4]) {
    __shared__ float As[16][68];
    __shared__ float Ws[16][68];
    const int tid = threadIdx.x;
    const int tx  = tid & 15;        // n sub-tile
    const int ty  = tid >> 4;        // m sub-tile
    const int lm  = tid >> 2;        // A load row (0..63)
    const int lk4 = (tid & 3) << 2;  // A load k offset (0,4,8,12)
    const int lkk = tid >> 4;        // W load k row (0..15)
    const int ln4 = (tid & 15) << 2; // W load n offset

    for (int k0 = 0; k0 < 512; k0 += 16) {
        float4 a = *(const float4*)(A + (size_t)(m0 + lm) * 512 + k0 + lk4);
        As[lk4 + 0][lm] = a.x;
        As[lk4 + 1][lm] = a.y;
        As[lk4 + 2][lm] = a.z;
        As[lk4 + 3][lm] = a.w;
        *(float4*)&Ws[lkk][ln4] =
            *(const float4*)(W + (size_t)(k0 + lkk) * N + n0 + ln4);
        __syncthreads();
#pragma unroll
        for (int kk = 0; kk < 16; kk++) {
            float4 a4 = *(const float4*)&As[kk][ty << 2];
            float4 b4 = *(const float4*)&Ws[kk][tx << 2];
            acc[0][0] = fmaf(a4.x, b4.x, acc[0][0]);
            acc[0][1] = fmaf(a4.x, b4.y, acc[0][1]);
            acc[0][2] = fmaf(a4.x, b4.z, acc[0][2]);
            acc[0][3] = fmaf(a4.x, b4.w, acc[0][3]);
            acc[1][0] = fmaf(a4.y, b4.x, acc[1][0]);
            acc[1][1] = fmaf(a4.y, b4.y, acc[1][1]);
            acc[1][2] = fmaf(a4.y, b4.z, acc[1][2]);
            acc[1][3] = fmaf(a4.y, b4.w, acc[1][3]);
            acc[2][0] = fmaf(a4.z, b4.x, acc[2][0]);
            acc[2][1] = fmaf(a4.z, b4.y, acc[2][1]);
            acc[2][2] = fmaf(a4.z, b4.z, acc[2][2]);
            acc[2][3] = fmaf(a4.z, b4.w, acc[2][3]);
            acc[3][0] = fmaf(a4.w, b4.x, acc[3][0]);
            acc[3][1] = fmaf(a4.w, b4.y, acc[3][1]);
            acc[3][2] = fmaf(a4.w, b4.z, acc[3][2]);
            acc[3][3] = fmaf(a4.w, b4.w, acc[3][3]);
        }
        __syncthreads();
    }
}

// ---------------- stage 1: all four input projections in one launch --------
__global__ __launch_bounds__(256)
void proj_kernel(const float* __restrict__ x,
                 const float* __restrict__ Wf, const float* __restrict__ bf,
                 const float* __restrict__ Wp, const float* __restrict__ bp,
                 const float* __restrict__ Wa, const float* __restrict__ ba,
                 const float* __restrict__ Wv, const float* __restrict__ bv) {
    const int z = blockIdx.z;   // 0:freq 1:phase 2:amp 3:v
    const float* W;  const float* bias;  int N;
    if      (z == 0) { W = Wf; bias = bf; N = 128; }
    else if (z == 1) { W = Wp; bias = bp; N = 128; }
    else if (z == 2) { W = Wa; bias = ba; N = 128; }
    else             { W = Wv; bias = bv; N = 512; }
    const int n0 = blockIdx.x * 64;
    if (n0 >= N) return;
    const int m0 = blockIdx.y * 64;

    float acc[4][4] = {};
    gemm_core(x, W, N, m0, n0, acc);

    const int tx = threadIdx.x & 15, ty = threadIdx.x >> 4;
#pragma unroll
    for (int i = 0; i < 4; i++) {
#pragma unroll
        for (int j = 0; j < 4; j++) {
            int m = m0 + (ty << 2) + i;
            int n = n0 + (tx << 2) + j;
            float c = acc[i][j] + bias[n];
            int b = m >> 9, t = m & 511;
            if (z == 3) {
                int h = n >> 6, d = n & 63;
                g_v[(((size_t)(b * 8 + h) * TL) + t) * HD + d] = c;
            } else {
                int h = n >> 4, w = n & 15;
                size_t idx = (((size_t)(b * 8 + h) * TL) + t) * WN + w;
                if (z == 0)      g_freq[idx]  = c;
                else if (z == 1) g_phase[idx] = c;
                else {
                    // softplus + eps, numerically stable
                    float sp = fmaxf(c, 0.0f) + log1pf(expf(-fabsf(c)));
                    g_amp[idx] = sp + 1e-8f;
                }
            }
        }
    }
}

// ---------------- S2 = sum_w amp^2 per (b,h,t) ----------------------------
__global__ __launch_bounds__(256)
void s2_kernel() {
    int i = blockIdx.x * 256 + threadIdx.x;
    if (i < BB * HN * TL) {
        const float* a = g_amp + (size_t)i * WN;
        float s = 0.f;
#pragma unroll
        for (int w = 0; w < WN; w++) s = fmaf(a[w], a[w], s);
        g_s2[i] = s;
    }
}

// ---------------- stage 2: interference attention fused with attn @ V -----
// grid: (16 bh, 16 q-tiles of 32), 256 threads: 32 q rows x 8 k-lanes
#define WAVE(FK, PK, AK, W_) {                                   \
    float dw  = fq_r[W_] - (FK);                                 \
    float dp  = pq_r[W_] - (PK);                                 \
    float arg = fmaf(dw, dt, dp);                                \
    float tr  = fmaf(arg, INV2PI, MAGIC);                        \
    float nn  = tr - MAGIC;                                      \
    float rr  = fmaf(nn, -C2PI_A, arg);                          \
    rr        = fmaf(nn, -C2PI_B, rr);                           \
    float cs  = __cosf(rr);                                      \
    float pp  = aq_r[W_] * (AK);                                 \
    dacc += pp;                                                  \
    cacc  = fmaf(pp, cs, cacc); }

__global__ __launch_bounds__(256)
void attn_av_kernel() {
    __shared__ float s_f[64 * 20];   // pitch 20: conflict-free float4 reads
    __shared__ float s_p[64 * 20];
    __shared__ float s_a[64 * 20];
    __shared__ float s_s2[64];
    __shared__ float s_v[64 * 68];   // pitch 68: conflict-free float4 reads

    const int bh  = blockIdx.x;                 // b*8+h
    const int q0  = (15 - blockIdx.y) * 32;     // heavy tiles launch first
    const int tid = threadIdx.x;
    const int ql  = tid >> 3;                   // q row in tile (0..31)
    const int sub = tid & 7;                    // k lane (0..7)
    const int q   = q0 + ql;

    // q-side registers
    float fq_r[16], pq_r[16], aq_r[16];
    {
        const float4* f4 = (const float4*)(g_freq  + ((size_t)bh * TL + q) * WN);
        const float4* p4 = (const float4*)(g_phase + ((size_t)bh * TL + q) * WN);
        const float4* a4 = (const float4*)(g_amp   + ((size_t)bh * TL + q) * WN);
#pragma unroll
        for (int i = 0; i < 4; i++) {
            float4 t;
            t = f4[i]; fq_r[4*i]=t.x; fq_r[4*i+1]=t.y; fq_r[4*i+2]=t.z; fq_r[4*i+3]=t.w;
            t = p4[i]; pq_r[4*i]=t.x; pq_r[4*i+1]=t.y; pq_r[4*i+2]=t.z; pq_r[4*i+3]=t.w;
            t = a4[i]; aq_r[4*i]=t.x; aq_r[4*i+1]=t.y; aq_r[4*i+2]=t.z; aq_r[4*i+3]=t.w;
        }
    }
    const float s2q = g_s2[(size_t)bh * TL + q];

    float out[64];
#pragma unroll
    for (int d = 0; d < 64; d++) out[d] = 0.f;

    const int kend = q0 + 32;                   // exclusive bound on k
#pragma unroll 1
    for (int kt = 0; kt < kend; kt += 64) {
        // ---- stage k tile to smem ----
        {
            const float4* fsrc = (const float4*)(g_freq  + ((size_t)bh * TL + kt) * WN);
            const float4* psrc = (const float4*)(g_phase + ((size_t)bh * TL + kt) * WN);
            const float4* asrc = (const float4*)(g_amp   + ((size_t)bh * TL + kt) * WN);
            int k  = tid >> 2;          // 0..63
            int c4 = (tid & 3) << 2;    // 0,4,8,12
            *(float4*)(s_f + k * 20 + c4) = fsrc[tid];
            *(float4*)(s_p + k * 20 + c4) = psrc[tid];
            *(float4*)(s_a + k * 20 + c4) = asrc[tid];
            const float4* vsrc = (const float4*)(g_v + ((size_t)bh * TL + kt) * HD);
#pragma unroll
            for (int l = tid; l < 1024; l += 256) {
                int r = l >> 4, cc = l & 15;
                *(float4*)(s_v + r * 68 + cc * 4) = vsrc[l];
            }
            if (tid < 64) s_s2[tid] = g_s2[(size_t)bh * TL + kt + tid];
        }
        __syncthreads();

#pragma unroll 1
        for (int j = 0; j < 8; j++) {
            int k = kt + sub + (j << 3);
            if (k <= q) {
                const float dt = (float)(q - k);
                const int   kr = k - kt;
                const float* fk = s_f + kr * 20;
                const float* pk = s_p + kr * 20;
                const float* ak = s_a + kr * 20;
                float cacc = 0.f, dacc = 0.f;
#pragma unroll
                for (int g = 0; g < 4; g++) {
                    float4 f4 = *(const float4*)(fk + g * 4);
                    float4 p4 = *(const float4*)(pk + g * 4);
                    float4 a4 = *(const float4*)(ak + g * 4);
                    WAVE(f4.x, p4.x, a4.x, g * 4 + 0);
                    WAVE(f4.y, p4.y, a4.y, g * 4 + 1);
                    WAVE(f4.z, p4.z, a4.z, g * 4 + 2);
                    WAVE(f4.w, p4.w, a4.w, g * 4 + 3);
                }
                float s2k    = s_s2[kr];
                float inten  = s2q + s2k + 2.f * cacc;
                float energy = s2q + s2k + 2.f * dacc + 1e-8f;
                float attn   = __fdividef(inten, energy);
                const float4* vr = (const float4*)(s_v + kr * 68);
#pragma unroll
                for (int d4 = 0; d4 < 16; d4++) {
                    float4 v4 = vr[d4];
                    out[4*d4+0] = fmaf(attn, v4.x, out[4*d4+0]);
                    out[4*d4+1] = fmaf(attn, v4.y, out[4*d4+1]);
                    out[4*d4+2] = fmaf(attn, v4.z, out[4*d4+2]);
                    out[4*d4+3] = fmaf(attn, v4.w, out[4*d4+3]);
                }
            }
        }
        __syncthreads();
    }

    // reduce the 8 k-lanes of each q row (lanes sub 0..7 are warp-contiguous)
#pragma unroll
    for (int d = 0; d < 64; d++) {
        float v = out[d];
        v += __shfl_xor_sync(0xffffffffu, v, 1);
        v += __shfl_xor_sync(0xffffffffu, v, 2);
        v += __shfl_xor_sync(0xffffffffu, v, 4);
        out[d] = v;
    }
    if (sub == 0) {
        int b = bh >> 3, h = bh & 7;
        float4* o4 = (float4*)(g_att + ((size_t)(b * TL + q) * DM) + h * HD);
#pragma unroll
        for (int d4 = 0; d4 < 16; d4++)
            o4[d4] = make_float4(out[4*d4], out[4*d4+1], out[4*d4+2], out[4*d4+3]);
    }
}

// ---------------- stage 3: final projection -------------------------------
__global__ __launch_bounds__(256)
void outproj_kernel(const float* __restrict__ Wo,
                    const float* __restrict__ bo,
                    float* __restrict__ y) {
    const int m0 = blockIdx.y * 64;
    const int n0 = blockIdx.x * 64;
    float acc[4][4] = {};
    gemm_core(g_att, Wo, 512, m0, n0, acc);
    const int tx = threadIdx.x & 15, ty = threadIdx.x >> 4;
#pragma unroll
    for (int i = 0; i < 4; i++) {
#pragma unroll
        for (int j = 0; j < 4; j++) {
            int m = m0 + (ty << 2) + i;
            int n = n0 + (tx << 2) + j;
            y[(size_t)m * 512 + n] = acc[i][j] + bo[n];
        }
    }
}

// ---------------- launch ---------------------------------------------------
extern "C" void kernel_launch(void* const* d_in, const int* in_sizes, int n_in,
                              void* d_out, int out_size) {
    const float* x  = (const float*)d_in[0];
    const float* Wf = (const float*)d_in[1];
    const float* bf = (const float*)d_in[2];
    const float* Wp = (const float*)d_in[3];
    const float* bp = (const float*)d_in[4];
    const float* Wa = (const float*)d_in[5];
    const float* ba = (const float*)d_in[6];
    const float* Wv = (const float*)d_in[7];
    const float* bv = (const float*)d_in[8];
    const float* Wo = (const float*)d_in[9];
    const float* bo = (const float*)d_in[10];
    float* y = (float*)d_out;

    proj_kernel<<<dim3(8, 16, 4), 256>>>(x, Wf, bf, Wp, bp, Wa, ba, Wv, bv);
    s2_kernel<<<32, 256>>>();
    attn_av_kernel<<<dim3(16, 16), 256>>>();
    outproj_kernel<<<dim3(8, 16), 256>>>(Wo, bo, y);
}

// round 4
// speedup vs baseline: 1.1668x; 1.1668x over previous
#include <cuda_runtime.h>

#define TL 512
#define WN 16
#define HD 64
#define DM 512

#define INV2PI 0.15915494309189535f
#define MAGIC  12582912.0f            // 1.5 * 2^23
#define C2PI_A 6.2831854820251465f
#define C2PI_B (-1.7484555e-7f)

// ---------------- static scratch (no allocation) ---------------------------
__device__ float g_freq [16*TL*WN];   // [bh][t][w]
__device__ float g_phase[16*TL*WN];
__device__ float g_amp  [16*TL*WN];
__device__ float g_v    [16*TL*HD];   // [bh][t][d]
__device__ float g_att0 [1024*DM];    // attn@V partial (k-split 0)
__device__ float g_att1 [1024*DM];    // attn@V partial (k-split 1)
__device__ float g_y0   [1024*DM];    // outproj partial (k-half 0)
__device__ float g_y1   [1024*DM];    // outproj partial (k-half 1)

// ---------------- GEMM core: 64x64 tile, BK=16, double-buffered ------------
// acc += A[m0:m0+64, kbeg:kend] * W[kbeg:kend, n0:n0+64]   (A is 1024x512)
// SUM2: A element = A0[i] + A1[i]
template<bool SUM2>
__device__ __forceinline__ void gemm64(const float* __restrict__ A0,
                                       const float* __restrict__ A1,
                                       const float* __restrict__ W, int ldw,
                                       int m0, int n0, int kbeg, int kend,
                                       float acc[4][4])
{
    __shared__ float As[2][16][68];
    __shared__ float Ws[2][16][68];
    const int tid = threadIdx.x;
    const int lm  = tid >> 2;          // A row within tile (0..63)
    const int lk4 = (tid & 3) << 2;    // A k offset (0,4,8,12)
    const int lkk = tid >> 4;          // W k row (0..15)
    const int ln4 = (tid & 15) << 2;   // W n offset
    const int tx  = tid & 15;
    const int ty  = tid >> 4;

    const float* Ar0 = A0 + (size_t)(m0 + lm) * DM + lk4;
    const float* Ar1 = A1 + (size_t)(m0 + lm) * DM + lk4;
    const float* Wb  = W + (size_t)lkk * ldw + n0 + ln4;

    // prefetch chunk 0
    float4 a = *(const float4*)(Ar0 + kbeg);
    if (SUM2) {
        float4 a2 = *(const float4*)(Ar1 + kbeg);
        a.x += a2.x; a.y += a2.y; a.z += a2.z; a.w += a2.w;
    }
    float4 w = *(const float4*)(Wb + (size_t)kbeg * ldw);

    int buf = 0;
#pragma unroll 1
    for (int k0 = kbeg; k0 < kend; k0 += 16) {
        As[buf][lk4 + 0][lm] = a.x;
        As[buf][lk4 + 1][lm] = a.y;
        As[buf][lk4 + 2][lm] = a.z;
        As[buf][lk4 + 3][lm] = a.w;
        *(float4*)&Ws[buf][lkk][ln4] = w;
        __syncthreads();
        if (k0 + 16 < kend) {   // prefetch next chunk (overlaps compute)
            a = *(const float4*)(Ar0 + k0 + 16);
            if (SUM2) {
                float4 a2 = *(const float4*)(Ar1 + k0 + 16);
                a.x += a2.x; a.y += a2.y; a.z += a2.z; a.w += a2.w;
            }
            w = *(const float4*)(Wb + (size_t)(k0 + 16) * ldw);
        }
#pragma unroll
        for (int kk = 0; kk < 16; kk++) {
            float4 a4 = *(const float4*)&As[buf][kk][ty << 2];
            float4 b4 = *(const float4*)&Ws[buf][kk][tx << 2];
            acc[0][0] = fmaf(a4.x, b4.x, acc[0][0]);
            acc[0][1] = fmaf(a4.x, b4.y, acc[0][1]);
            acc[0][2] = fmaf(a4.x, b4.z, acc[0][2]);
            acc[0][3] = fmaf(a4.x, b4.w, acc[0][3]);
            acc[1][0] = fmaf(a4.y, b4.x, acc[1][0]);
            acc[1][1] = fmaf(a4.y, b4.y, acc[1][1]);
            acc[1][2] = fmaf(a4.y, b4.z, acc[1][2]);
            acc[1][3] = fmaf(a4.y, b4.w, acc[1][3]);
            acc[2][0] = fmaf(a4.z, b4.x, acc[2][0]);
            acc[2][1] = fmaf(a4.z, b4.y, acc[2][1]);
            acc[2][2] = fmaf(a4.z, b4.z, acc[2][2]);
            acc[2][3] = fmaf(a4.z, b4.w, acc[2][3]);
            acc[3][0] = fmaf(a4.w, b4.x, acc[3][0]);
            acc[3][1] = fmaf(a4.w, b4.y, acc[3][1]);
            acc[3][2] = fmaf(a4.w, b4.z, acc[3][2]);
            acc[3][3] = fmaf(a4.w, b4.w, acc[3][3]);
        }
        buf ^= 1;
    }
}

// ---------------- stage 1: all four projections, no dead CTAs --------------
// grid (14, 16): n-tiles 0-1 freq, 2-3 phase, 4-5 amp, 6-13 v
__global__ __launch_bounds__(256)
void proj2_kernel(const float* __restrict__ x,
                  const float* __restrict__ Wf, const float* __restrict__ bf,
                  const float* __restrict__ Wp, const float* __restrict__ bp,
                  const float* __restrict__ Wa, const float* __restrict__ ba,
                  const float* __restrict__ Wv, const float* __restrict__ bv)
{
    const int nt = blockIdx.x;
    const int m0 = blockIdx.y * 64;
    const float* W; const float* bias; int ldw, nc0, kind;
    if      (nt < 2) { W = Wf; bias = bf; ldw = 128; nc0 = nt*64;       kind = 0; }
    else if (nt < 4) { W = Wp; bias = bp; ldw = 128; nc0 = nt*64 - 128; kind = 1; }
    else if (nt < 6) { W = Wa; bias = ba; ldw = 128; nc0 = nt*64 - 256; kind = 2; }
    else             { W = Wv; bias = bv; ldw = 512; nc0 = nt*64 - 384; kind = 3; }

    float acc[4][4] = {};
    gemm64<false>(x, x, W, ldw, m0, nc0, 0, 512, acc);

    const int tx = threadIdx.x & 15, ty = threadIdx.x >> 4;
#pragma unroll
    for (int i = 0; i < 4; i++) {
#pragma unroll
        for (int j = 0; j < 4; j++) {
            int m = m0 + (ty << 2) + i;
            int n = nc0 + (tx << 2) + j;
            float c = acc[i][j] + bias[n];
            int b = m >> 9, t = m & 511;
            if (kind == 3) {
                int h = n >> 6, d = n & 63;
                g_v[(((size_t)(b*8 + h) * TL) + t) * HD + d] = c;
            } else {
                int h = n >> 4, w_ = n & 15;
                size_t idx = (((size_t)(b*8 + h) * TL) + t) * WN + w_;
                if (kind == 0)      g_freq[idx]  = c;
                else if (kind == 1) g_phase[idx] = c;
                else {
                    float sp = fmaxf(c, 0.0f) + log1pf(expf(-fabsf(c)));
                    g_amp[idx] = sp + 1e-8f;
                }
            }
        }
    }
}

// ---------------- stage 2: interference attention, tiled ------------------
// grid (16 bh, 8 q-tiles reversed, 2 k-splits), 256 threads
// phase A: 64x64 attn tile -> smem (transposed [k][q])
// phase B: 4x4-blocked GEMM  attn_tile @ V_tile -> acc regs
#define WAVE(FK, PK, AK, W_) {                                   \
    float dw  = fq[W_] - (FK);                                   \
    float dp  = pq[W_] - (PK);                                   \
    float arg = fmaf(dw, dtv, dp);                               \
    float nn  = fmaf(arg, INV2PI, MAGIC) - MAGIC;                \
    float rr  = fmaf(nn, -C2PI_A, arg);                          \
    rr        = fmaf(nn, -C2PI_B, rr);                           \
    float cs  = __cosf(rr);                                      \
    float pp  = aq[W_] * (AK);                                   \
    dacc += pp;                                                  \
    cacc  = fmaf(pp, cs, cacc); }

__global__ __launch_bounds__(256, 2)
void attn2_kernel()
{
    __shared__ float s_fpa[64 * 52];   // per k row: 16 f | 16 p | 16 a | pad 4
    __shared__ float s_s2p[64 * 4];    // per k row: 4 partial sums of a^2
    __shared__ float s_att[64 * 68];   // [k][q], transposed
    __shared__ float s_v  [64 * 68];   // [k][d]

    const int bh = blockIdx.x;               // b*8+h
    const int qt = 7 - blockIdx.y;           // heavy q-tiles launch first
    const int s  = blockIdx.z;               // k-split
    const int tid = threadIdx.x;
    const int qa = tid >> 2;                 // phase A q row (0..63)
    const int g  = tid & 3;                  // phase A k lane
    const int ty = tid >> 4;                 // phase B q group
    const int tx = tid & 15;                 // phase B d group
    const int qglob = qt * 64 + qa;
    const int b = bh >> 3, h = bh & 7;

    // q-side params in registers
    float fq[16], pq[16], aq[16];
    {
        const float4* f4 = (const float4*)(g_freq  + (((size_t)bh*TL) + qglob) * WN);
        const float4* p4 = (const float4*)(g_phase + (((size_t)bh*TL) + qglob) * WN);
        const float4* a4 = (const float4*)(g_amp   + (((size_t)bh*TL) + qglob) * WN);
#pragma unroll
        for (int i = 0; i < 4; i++) {
            float4 t;
            t = f4[i]; fq[4*i]=t.x; fq[4*i+1]=t.y; fq[4*i+2]=t.z; fq[4*i+3]=t.w;
            t = p4[i]; pq[4*i]=t.x; pq[4*i+1]=t.y; pq[4*i+2]=t.z; pq[4*i+3]=t.w;
            t = a4[i]; aq[4*i]=t.x; aq[4*i+1]=t.y; aq[4*i+2]=t.z; aq[4*i+3]=t.w;
        }
    }
    float s2q = 0.f;
#pragma unroll
    for (int i = 0; i < 16; i++) s2q = fmaf(aq[i], aq[i], s2q);

    float acc[4][4] = {};

#pragma unroll 1
    for (int kt = s * 64; kt < (qt + 1) * 64; kt += 128) {
        __syncthreads();   // protect smem reuse from previous phase B
        // ---- stage k-tile: fpa + per-row a^2 partials + V ----
        {
            int row = tid >> 2, c4 = (tid & 3) << 2;
            size_t base = ((size_t)bh * TL + (kt + row)) * WN + c4;
            float4 f = *(const float4*)(g_freq  + base);
            float4 p = *(const float4*)(g_phase + base);
            float4 a = *(const float4*)(g_amp   + base);
            *(float4*)&s_fpa[row*52 +      c4] = f;
            *(float4*)&s_fpa[row*52 + 16 + c4] = p;
            *(float4*)&s_fpa[row*52 + 32 + c4] = a;
            s_s2p[row*4 + (tid & 3)] =
                a.x*a.x + a.y*a.y + a.z*a.z + a.w*a.w;
#pragma unroll
            for (int i = 0; i < 4; i++) {
                int l = tid + i * 256;
                int r = l >> 4, cc = (l & 15) << 2;
                *(float4*)&s_v[r*68 + cc] =
                    *(const float4*)(g_v + ((size_t)bh*TL + (kt + r)) * HD + cc);
            }
        }
        __syncthreads();

        // ---- phase A: attn tile ----
#pragma unroll 1
        for (int j = 0; j < 16; j++) {
            int kl = g + (j << 2);
            int kg = kt + kl;
            float attv = 0.f;
            if (kg <= qglob) {
                const float dtv = (float)(qglob - kg);
                const float* fk = &s_fpa[kl * 52];
                float4 s2p = *(const float4*)&s_s2p[kl * 4];
                float s2k = (s2p.x + s2p.y) + (s2p.z + s2p.w);
                float cacc = 0.f, dacc = 0.f;
#pragma unroll
                for (int g4 = 0; g4 < 4; g4++) {
                    float4 f4 = *(const float4*)(fk +      (g4 << 2));
                    float4 p4 = *(const float4*)(fk + 16 + (g4 << 2));
                    float4 a4 = *(const float4*)(fk + 32 + (g4 << 2));
                    WAVE(f4.x, p4.x, a4.x, (g4<<2) + 0);
                    WAVE(f4.y, p4.y, a4.y, (g4<<2) + 1);
                    WAVE(f4.z, p4.z, a4.z, (g4<<2) + 2);
                    WAVE(f4.w, p4.w, a4.w, (g4<<2) + 3);
                }
                float S  = s2q + s2k;
                float it = fmaf(2.f, cacc, S);
                float en = fmaf(2.f, dacc, S) + 1e-8f;
                attv = __fdividef(it, en);
            }
            s_att[kl * 68 + qa] = attv;
        }
        __syncthreads();

        // ---- phase B: acc += attn_tile^T-read @ V_tile ----
#pragma unroll 4
        for (int kk = 0; kk < 64; kk++) {
            float4 a4 = *(const float4*)&s_att[kk*68 + (ty << 2)];
            float4 v4 = *(const float4*)&s_v  [kk*68 + (tx << 2)];
            acc[0][0] = fmaf(a4.x, v4.x, acc[0][0]);
            acc[0][1] = fmaf(a4.x, v4.y, acc[0][1]);
            acc[0][2] = fmaf(a4.x, v4.z, acc[0][2]);
            acc[0][3] = fmaf(a4.x, v4.w, acc[0][3]);
            acc[1][0] = fmaf(a4.y, v4.x, acc[1][0]);
            acc[1][1] = fmaf(a4.y, v4.y, acc[1][1]);
            acc[1][2] = fmaf(a4.y, v4.z, acc[1][2]);
            acc[1][3] = fmaf(a4.y, v4.w, acc[1][3]);
            acc[2][0] = fmaf(a4.z, v4.x, acc[2][0]);
            acc[2][1] = fmaf(a4.z, v4.y, acc[2][1]);
            acc[2][2] = fmaf(a4.z, v4.z, acc[2][2]);
            acc[2][3] = fmaf(a4.z, v4.w, acc[2][3]);
            acc[3][0] = fmaf(a4.w, v4.x, acc[3][0]);
            acc[3][1] = fmaf(a4.w, v4.y, acc[3][1]);
            acc[3][2] = fmaf(a4.w, v4.z, acc[3][2]);
            acc[3][3] = fmaf(a4.w, v4.w, acc[3][3]);
        }
    }

    // ---- epilogue: write 4x4 block (zero if this split had no tiles) ----
    float* dst = s ? g_att1 : g_att0;
#pragma unroll
    for (int i = 0; i < 4; i++) {
        int row = qt * 64 + (ty << 2) + i;
        *(float4*)&dst[((size_t)(b * TL + row)) * DM + h * HD + (tx << 2)] =
            make_float4(acc[i][0], acc[i][1], acc[i][2], acc[i][3]);
    }
}

// ---------------- stage 3: output projection, split-K=2 -------------------
__global__ __launch_bounds__(256)
void outp2_kernel(const float* __restrict__ Wo)
{
    const int n0 = blockIdx.x * 64;
    const int m0 = blockIdx.y * 64;
    const int z  = blockIdx.z;
    float acc[4][4] = {};
    gemm64<true>(g_att0, g_att1, Wo, 512, m0, n0, z * 256, z * 256 + 256, acc);
    float* dst = z ? g_y1 : g_y0;
    const int tx = threadIdx.x & 15, ty = threadIdx.x >> 4;
#pragma unroll
    for (int i = 0; i < 4; i++) {
        int m = m0 + (ty << 2) + i;
        *(float4*)&dst[(size_t)m * DM + n0 + (tx << 2)] =
            make_float4(acc[i][0], acc[i][1], acc[i][2], acc[i][3]);
    }
}

__global__ __launch_bounds__(256)
void addbias_kernel(const float* __restrict__ bo, float* __restrict__ y)
{
    int i = blockIdx.x * 256 + threadIdx.x;      // float4 index, 131072 total
    float4 a = ((const float4*)g_y0)[i];
    float4 c = ((const float4*)g_y1)[i];
    int col = (i << 2) & 511;
    float4 bb = *(const float4*)(bo + col);
    ((float4*)y)[i] = make_float4(a.x + c.x + bb.x, a.y + c.y + bb.y,
                                  a.z + c.z + bb.z, a.w + c.w + bb.w);
}

// ---------------- launch ---------------------------------------------------
extern "C" void kernel_launch(void* const* d_in, const int* in_sizes, int n_in,
                              void* d_out, int out_size)
{
    const float* x  = (const float*)d_in[0];
    const float* Wf = (const float*)d_in[1];
    const float* bf = (const float*)d_in[2];
    const float* Wp = (const float*)d_in[3];
    const float* bp = (const float*)d_in[4];
    const float* Wa = (const float*)d_in[5];
    const float* ba = (const float*)d_in[6];
    const float* Wv = (const float*)d_in[7];
    const float* bv = (const float*)d_in[8];
    const float* Wo = (const float*)d_in[9];
    const float* bo = (const float*)d_in[10];
    float* y = (float*)d_out;

    proj2_kernel<<<dim3(14, 16), 256>>>(x, Wf, bf, Wp, bp, Wa, ba, Wv, bv);
    attn2_kernel<<<dim3(16, 8, 2), 256>>>();
    outp2_kernel<<<dim3(8, 16, 2), 256>>>(Wo);
    addbias_kernel<<<512, 256>>>(bo, y);
}

// round 5
// speedup vs baseline: 1.2310x; 1.0550x over previous
#include <cuda_runtime.h>

#define TL 512
#define WN 16
#define HD 64
#define DM 512
#define ATT_SZ (1024 * DM)

#define INV2PI 0.15915494309189535f
#define MAGIC  12582912.0f            // 1.5 * 2^23
#define C2PI_A 6.2831854820251465f
#define C2PI_B (-1.7484555e-7f)

// ---------------- static scratch (no allocation) ---------------------------
__device__ float g_freq [16*TL*WN];   // [bh][t][w]
__device__ float g_phase[16*TL*WN];
__device__ float g_amp  [16*TL*WN];
__device__ float g_v    [16*TL*HD];   // [bh][t][d]
__device__ float g_att4 [4*ATT_SZ];   // attn@V partials, 4 k-splits

// ---------------- GEMM core (single A): 64x64 tile, BK=16, dbl-buffered ----
__device__ __forceinline__ void gemm64(const float* __restrict__ A,
                                       const float* __restrict__ W, int ldw,
                                       int m0, int n0,
                                       float acc[4][4])
{
    __shared__ float As[2][16][68];
    __shared__ float Ws[2][16][68];
    const int tid = threadIdx.x;
    const int lm  = tid >> 2;          // A row within tile (0..63)
    const int lk4 = (tid & 3) << 2;    // A k offset (0,4,8,12)
    const int lkk = tid >> 4;          // W k row (0..15)
    const int ln4 = (tid & 15) << 2;   // W n offset
    const int tx  = tid & 15;
    const int ty  = tid >> 4;

    const float* Ar = A + (size_t)(m0 + lm) * DM + lk4;
    const float* Wb = W + (size_t)lkk * ldw + n0 + ln4;

    float4 a = *(const float4*)(Ar);
    float4 w = *(const float4*)(Wb);

    int buf = 0;
#pragma unroll 1
    for (int k0 = 0; k0 < 512; k0 += 16) {
        As[buf][lk4 + 0][lm] = a.x;
        As[buf][lk4 + 1][lm] = a.y;
        As[buf][lk4 + 2][lm] = a.z;
        As[buf][lk4 + 3][lm] = a.w;
        *(float4*)&Ws[buf][lkk][ln4] = w;
        __syncthreads();
        if (k0 + 16 < 512) {
            a = *(const float4*)(Ar + k0 + 16);
            w = *(const float4*)(Wb + (size_t)(k0 + 16) * ldw);
        }
#pragma unroll
        for (int kk = 0; kk < 16; kk++) {
            float4 a4 = *(const float4*)&As[buf][kk][ty << 2];
            float4 b4 = *(const float4*)&Ws[buf][kk][tx << 2];
            acc[0][0] = fmaf(a4.x, b4.x, acc[0][0]);
            acc[0][1] = fmaf(a4.x, b4.y, acc[0][1]);
            acc[0][2] = fmaf(a4.x, b4.z, acc[0][2]);
            acc[0][3] = fmaf(a4.x, b4.w, acc[0][3]);
            acc[1][0] = fmaf(a4.y, b4.x, acc[1][0]);
            acc[1][1] = fmaf(a4.y, b4.y, acc[1][1]);
            acc[1][2] = fmaf(a4.y, b4.z, acc[1][2]);
            acc[1][3] = fmaf(a4.y, b4.w, acc[1][3]);
            acc[2][0] = fmaf(a4.z, b4.x, acc[2][0]);
            acc[2][1] = fmaf(a4.z, b4.y, acc[2][1]);
            acc[2][2] = fmaf(a4.z, b4.z, acc[2][2]);
            acc[2][3] = fmaf(a4.z, b4.w, acc[2][3]);
            acc[3][0] = fmaf(a4.w, b4.x, acc[3][0]);
            acc[3][1] = fmaf(a4.w, b4.y, acc[3][1]);
            acc[3][2] = fmaf(a4.w, b4.z, acc[3][2]);
            acc[3][3] = fmaf(a4.w, b4.w, acc[3][3]);
        }
        buf ^= 1;
    }
}

// ---------------- stage 1: all four projections, no dead CTAs --------------
// grid (14, 16): n-tiles 0-1 freq, 2-3 phase, 4-5 amp, 6-13 v
__global__ __launch_bounds__(256)
void proj2_kernel(const float* __restrict__ x,
                  const float* __restrict__ Wf, const float* __restrict__ bf,
                  const float* __restrict__ Wp, const float* __restrict__ bp,
                  const float* __restrict__ Wa, const float* __restrict__ ba,
                  const float* __restrict__ Wv, const float* __restrict__ bv)
{
    const int nt = blockIdx.x;
    const int m0 = blockIdx.y * 64;
    const float* W; const float* bias; int ldw, nc0, kind;
    if      (nt < 2) { W = Wf; bias = bf; ldw = 128; nc0 = nt*64;       kind = 0; }
    else if (nt < 4) { W = Wp; bias = bp; ldw = 128; nc0 = nt*64 - 128; kind = 1; }
    else if (nt < 6) { W = Wa; bias = ba; ldw = 128; nc0 = nt*64 - 256; kind = 2; }
    else             { W = Wv; bias = bv; ldw = 512; nc0 = nt*64 - 384; kind = 3; }

    float acc[4][4] = {};
    gemm64(x, W, ldw, m0, nc0, acc);

    const int tx = threadIdx.x & 15, ty = threadIdx.x >> 4;
#pragma unroll
    for (int i = 0; i < 4; i++) {
#pragma unroll
        for (int j = 0; j < 4; j++) {
            int m = m0 + (ty << 2) + i;
            int n = nc0 + (tx << 2) + j;
            float c = acc[i][j] + bias[n];
            int b = m >> 9, t = m & 511;
            if (kind == 3) {
                int h = n >> 6, d = n & 63;
                g_v[(((size_t)(b*8 + h) * TL) + t) * HD + d] = c;
            } else {
                int h = n >> 4, w_ = n & 15;
                size_t idx = (((size_t)(b*8 + h) * TL) + t) * WN + w_;
                if (kind == 0)      g_freq[idx]  = c;
                else if (kind == 1) g_phase[idx] = c;
                else {
                    float sp = fmaxf(c, 0.0f) + log1pf(expf(-fabsf(c)));
                    g_amp[idx] = sp + 1e-8f;
                }
            }
        }
    }
}

// ---------------- stage 2: interference attention, tiled ------------------
// grid (16 bh, 8 q-tiles reversed, 4 k-splits), 256 threads
#define WAVE(FK, PK, AK, W_) {                                   \
    float dw  = fq[W_] - (FK);                                   \
    float dp  = pq[W_] - (PK);                                   \
    float arg = fmaf(dw, dtv, dp);                               \
    float nn  = fmaf(arg, INV2PI, MAGIC) - MAGIC;                \
    float rr  = fmaf(nn, -C2PI_A, arg);                          \
    rr        = fmaf(nn, -C2PI_B, rr);                           \
    float cs  = __cosf(rr);                                      \
    float pp  = aq[W_] * (AK);                                   \
    dacc += pp;                                                  \
    cacc  = fmaf(pp, cs, cacc); }

__global__ __launch_bounds__(256, 2)
void attn4_kernel()
{
    __shared__ float s_fpa[64 * 52];   // per k row: 16 f | 16 p | 16 a | pad 4
    __shared__ float s_s2p[64 * 4];    // per k row: 4 partial sums of a^2
    __shared__ float s_att[64 * 68];   // [k][q], transposed
    __shared__ float s_v  [64 * 68];   // [k][d]

    const int bh = blockIdx.x;               // b*8+h
    const int qt = 7 - blockIdx.y;           // heavy q-tiles launch first
    const int s  = blockIdx.z;               // k-split (0..3)
    const int tid = threadIdx.x;
    const int qa = tid >> 2;                 // phase A q row (0..63)
    const int g  = tid & 3;                  // phase A k lane
    const int ty = tid >> 4;                 // phase B q group
    const int tx = tid & 15;                 // phase B d group
    const int qglob = qt * 64 + qa;
    const int b = bh >> 3, h = bh & 7;

    // q-side params in registers
    float fq[16], pq[16], aq[16];
    {
        const float4* f4 = (const float4*)(g_freq  + (((size_t)bh*TL) + qglob) * WN);
        const float4* p4 = (const float4*)(g_phase + (((size_t)bh*TL) + qglob) * WN);
        const float4* a4 = (const float4*)(g_amp   + (((size_t)bh*TL) + qglob) * WN);
#pragma unroll
        for (int i = 0; i < 4; i++) {
            float4 t;
            t = f4[i]; fq[4*i]=t.x; fq[4*i+1]=t.y; fq[4*i+2]=t.z; fq[4*i+3]=t.w;
            t = p4[i]; pq[4*i]=t.x; pq[4*i+1]=t.y; pq[4*i+2]=t.z; pq[4*i+3]=t.w;
            t = a4[i]; aq[4*i]=t.x; aq[4*i+1]=t.y; aq[4*i+2]=t.z; aq[4*i+3]=t.w;
        }
    }
    float s2q = 0.f;
#pragma unroll
    for (int i = 0; i < 16; i++) s2q = fmaf(aq[i], aq[i], s2q);

    float acc[4][4] = {};

#pragma unroll 1
    for (int kt = s * 64; kt < (qt + 1) * 64; kt += 256) {
        __syncthreads();   // protect smem reuse from previous phase B
        // ---- stage k-tile: fpa + per-row a^2 partials + V ----
        {
            int row = tid >> 2, c4 = (tid & 3) << 2;
            size_t base = ((size_t)bh * TL + (kt + row)) * WN + c4;
            float4 f = *(const float4*)(g_freq  + base);
            float4 p = *(const float4*)(g_phase + base);
            float4 a = *(const float4*)(g_amp   + base);
            *(float4*)&s_fpa[row*52 +      c4] = f;
            *(float4*)&s_fpa[row*52 + 16 + c4] = p;
            *(float4*)&s_fpa[row*52 + 32 + c4] = a;
            s_s2p[row*4 + (tid & 3)] =
                a.x*a.x + a.y*a.y + a.z*a.z + a.w*a.w;
#pragma unroll
            for (int i = 0; i < 4; i++) {
                int l = tid + i * 256;
                int r = l >> 4, cc = (l & 15) << 2;
                *(float4*)&s_v[r*68 + cc] =
                    *(const float4*)(g_v + ((size_t)bh*TL + (kt + r)) * HD + cc);
            }
        }
        __syncthreads();

        // ---- phase A: attn tile ----
#pragma unroll 1
        for (int j = 0; j < 16; j++) {
            int kl = g + (j << 2);
            int kg = kt + kl;
            float attv = 0.f;
            if (kg <= qglob) {
                const float dtv = (float)(qglob - kg);
                const float* fk = &s_fpa[kl * 52];
                float4 s2p = *(const float4*)&s_s2p[kl * 4];
                float s2k = (s2p.x + s2p.y) + (s2p.z + s2p.w);
                float cacc = 0.f, dacc = 0.f;
#pragma unroll
                for (int g4 = 0; g4 < 4; g4++) {
                    float4 f4 = *(const float4*)(fk +      (g4 << 2));
                    float4 p4 = *(const float4*)(fk + 16 + (g4 << 2));
                    float4 a4 = *(const float4*)(fk + 32 + (g4 << 2));
                    WAVE(f4.x, p4.x, a4.x, (g4<<2) + 0);
                    WAVE(f4.y, p4.y, a4.y, (g4<<2) + 1);
                    WAVE(f4.z, p4.z, a4.z, (g4<<2) + 2);
                    WAVE(f4.w, p4.w, a4.w, (g4<<2) + 3);
                }
                float S  = s2q + s2k;
                float it = fmaf(2.f, cacc, S);
                float en = fmaf(2.f, dacc, S) + 1e-8f;
                attv = __fdividef(it, en);
            }
            s_att[kl * 68 + qa] = attv;
        }
        __syncthreads();

        // ---- phase B: acc += attn_tile^T-read @ V_tile ----
#pragma unroll 4
        for (int kk = 0; kk < 64; kk++) {
            float4 a4 = *(const float4*)&s_att[kk*68 + (ty << 2)];
            float4 v4 = *(const float4*)&s_v  [kk*68 + (tx << 2)];
            acc[0][0] = fmaf(a4.x, v4.x, acc[0][0]);
            acc[0][1] = fmaf(a4.x, v4.y, acc[0][1]);
            acc[0][2] = fmaf(a4.x, v4.z, acc[0][2]);
            acc[0][3] = fmaf(a4.x, v4.w, acc[0][3]);
            acc[1][0] = fmaf(a4.y, v4.x, acc[1][0]);
            acc[1][1] = fmaf(a4.y, v4.y, acc[1][1]);
            acc[1][2] = fmaf(a4.y, v4.z, acc[1][2]);
            acc[1][3] = fmaf(a4.y, v4.w, acc[1][3]);
            acc[2][0] = fmaf(a4.z, v4.x, acc[2][0]);
            acc[2][1] = fmaf(a4.z, v4.y, acc[2][1]);
            acc[2][2] = fmaf(a4.z, v4.z, acc[2][2]);
            acc[2][3] = fmaf(a4.z, v4.w, acc[2][3]);
            acc[3][0] = fmaf(a4.w, v4.x, acc[3][0]);
            acc[3][1] = fmaf(a4.w, v4.y, acc[3][1]);
            acc[3][2] = fmaf(a4.w, v4.z, acc[3][2]);
            acc[3][3] = fmaf(a4.w, v4.w, acc[3][3]);
        }
    }

    // ---- epilogue: write 4x4 block (zeros if this split had no tiles) ----
    float* dst = g_att4 + (size_t)s * ATT_SZ;
#pragma unroll
    for (int i = 0; i < 4; i++) {
        int row = qt * 64 + (ty << 2) + i;
        *(float4*)&dst[((size_t)(b * TL + row)) * DM + h * HD + (tx << 2)] =
            make_float4(acc[i][0], acc[i][1], acc[i][2], acc[i][3]);
    }
}

// ---------------- stage 3: output projection (4-way A-sum, fused bias) -----
__global__ __launch_bounds__(256)
void outp4_kernel(const float* __restrict__ Wo,
                  const float* __restrict__ bo,
                  float* __restrict__ y)
{
    __shared__ float As[2][16][68];
    __shared__ float Ws[2][16][68];
    const int n0 = blockIdx.x * 64;
    const int m0 = blockIdx.y * 64;
    const int tid = threadIdx.x;
    const int lm  = tid >> 2;
    const int lk4 = (tid & 3) << 2;
    const int lkk = tid >> 4;
    const int ln4 = (tid & 15) << 2;
    const int tx  = tid & 15;
    const int ty  = tid >> 4;

    const size_t abase = (size_t)(m0 + lm) * DM + lk4;
    const float* Wb = Wo + (size_t)lkk * DM + n0 + ln4;

    float acc[4][4] = {};

    // prefetch chunk 0: 4-buffer sum
    float4 a;
    {
        float4 a0 = *(const float4*)(g_att4 + 0*ATT_SZ + abase);
        float4 a1 = *(const float4*)(g_att4 + 1*ATT_SZ + abase);
        float4 a2 = *(const float4*)(g_att4 + 2*ATT_SZ + abase);
        float4 a3 = *(const float4*)(g_att4 + 3*ATT_SZ + abase);
        a = make_float4((a0.x+a1.x)+(a2.x+a3.x), (a0.y+a1.y)+(a2.y+a3.y),
                        (a0.z+a1.z)+(a2.z+a3.z), (a0.w+a1.w)+(a2.w+a3.w));
    }
    float4 w = *(const float4*)(Wb);

    int buf = 0;
#pragma unroll 1
    for (int k0 = 0; k0 < 512; k0 += 16) {
        As[buf][lk4 + 0][lm] = a.x;
        As[buf][lk4 + 1][lm] = a.y;
        As[buf][lk4 + 2][lm] = a.z;
        As[buf][lk4 + 3][lm] = a.w;
        *(float4*)&Ws[buf][lkk][ln4] = w;
        __syncthreads();
        if (k0 + 16 < 512) {
            float4 a0 = *(const float4*)(g_att4 + 0*ATT_SZ + abase + k0 + 16);
            float4 a1 = *(const float4*)(g_att4 + 1*ATT_SZ + abase + k0 + 16);
            float4 a2 = *(const float4*)(g_att4 + 2*ATT_SZ + abase + k0 + 16);
            float4 a3 = *(const float4*)(g_att4 + 3*ATT_SZ + abase + k0 + 16);
            a = make_float4((a0.x+a1.x)+(a2.x+a3.x), (a0.y+a1.y)+(a2.y+a3.y),
                            (a0.z+a1.z)+(a2.z+a3.z), (a0.w+a1.w)+(a2.w+a3.w));
            w = *(const float4*)(Wb + (size_t)(k0 + 16) * DM);
        }
#pragma unroll
        for (int kk = 0; kk < 16; kk++) {
            float4 a4 = *(const float4*)&As[buf][kk][ty << 2];
            float4 b4 = *(const float4*)&Ws[buf][kk][tx << 2];
            acc[0][0] = fmaf(a4.x, b4.x, acc[0][0]);
            acc[0][1] = fmaf(a4.x, b4.y, acc[0][1]);
            acc[0][2] = fmaf(a4.x, b4.z, acc[0][2]);
            acc[0][3] = fmaf(a4.x, b4.w, acc[0][3]);
            acc[1][0] = fmaf(a4.y, b4.x, acc[1][0]);
            acc[1][1] = fmaf(a4.y, b4.y, acc[1][1]);
            acc[1][2] = fmaf(a4.y, b4.z, acc[1][2]);
            acc[1][3] = fmaf(a4.y, b4.w, acc[1][3]);
            acc[2][0] = fmaf(a4.z, b4.x, acc[2][0]);
            acc[2][1] = fmaf(a4.z, b4.y, acc[2][1]);
            acc[2][2] = fmaf(a4.z, b4.z, acc[2][2]);
            acc[2][3] = fmaf(a4.z, b4.w, acc[2][3]);
            acc[3][0] = fmaf(a4.w, b4.x, acc[3][0]);
            acc[3][1] = fmaf(a4.w, b4.y, acc[3][1]);
            acc[3][2] = fmaf(a4.w, b4.z, acc[3][2]);
            acc[3][3] = fmaf(a4.w, b4.w, acc[3][3]);
        }
        buf ^= 1;
    }

    // epilogue: fused bias, direct write to y
#pragma unroll
    for (int i = 0; i < 4; i++) {
        int m = m0 + (ty << 2) + i;
        int n = n0 + (tx << 2);
        float4 bb = *(const float4*)(bo + n);
        *(float4*)&y[(size_t)m * DM + n] =
            make_float4(acc[i][0] + bb.x, acc[i][1] + bb.y,
                        acc[i][2] + bb.z, acc[i][3] + bb.w);
    }
}

// ---------------- launch ---------------------------------------------------
extern "C" void kernel_launch(void* const* d_in, const int* in_sizes, int n_in,
                              void* d_out, int out_size)
{
    const float* x  = (const float*)d_in[0];
    const float* Wf = (const float*)d_in[1];
    const float* bf = (const float*)d_in[2];
    const float* Wp = (const float*)d_in[3];
    const float* bp = (const float*)d_in[4];
    const float* Wa = (const float*)d_in[5];
    const float* ba = (const float*)d_in[6];
    const float* Wv = (const float*)d_in[7];
    const float* bv = (const float*)d_in[8];
    const float* Wo = (const float*)d_in[9];
    const float* bo = (const float*)d_in[10];
    float* y = (float*)d_out;

    proj2_kernel<<<dim3(14, 16), 256>>>(x, Wf, bf, Wp, bp, Wa, ba, Wv, bv);
    attn4_kernel<<<dim3(16, 8, 4), 256>>>();
    outp4_kernel<<<dim3(8, 16), 256>>>(Wo, bo, y);
}